// round 13
// baseline (speedup 1.0000x reference)
#include <cuda_runtime.h>
#include <cuda_fp16.h>
#include <cstdint>

#define BB 4
#define LL 4096
#define DD 768
#define ML (BB*LL)

// ---------------- scratch (__device__ globals; allocation-free contract) ----
__device__ __half g_Xh[(size_t)ML * DD], g_Xl[(size_t)ML * DD];
__device__ __half g_Wth[3][(size_t)DD * DD], g_Wtl[3][(size_t)DD * DD];
__device__ __half g_Qh[(size_t)ML * DD], g_Ql[(size_t)ML * DD];
__device__ __half g_Kh[(size_t)ML * DD], g_Kl[(size_t)ML * DD];
__device__ __half g_Vt[(size_t)ML * DD];              // [b][d][l] fp16
__device__ float  g_S [(size_t)BB * LL * LL];
__device__ __half g_P [(size_t)BB * LL * LL];

// ---------------- helpers (base-family ISA only) -----------------------------
__device__ __forceinline__ uint32_t s2u(const void* p) {
    uint32_t a;
    asm("{ .reg .u64 t; cvta.to.shared.u64 t, %1; cvt.u32.u64 %0, t; }"
        : "=r"(a) : "l"(p));
    return a;
}
__device__ __forceinline__ uint32_t sw128(uint32_t off) {
    return off ^ ((off >> 3) & 0x70);
}
__device__ __forceinline__ void cp16(uint32_t saddr, const void* g) {
    asm volatile("cp.async.cg.shared.global [%0], [%1], 16;" :: "r"(saddr), "l"(g));
}
__device__ __forceinline__ void cp_commit() {
    asm volatile("cp.async.commit_group;");
}
template <int N>
__device__ __forceinline__ void cp_wait() {
    asm volatile("cp.async.wait_group %0;" :: "n"(N));
}
__device__ __forceinline__ void ldm_x4(uint32_t* r, uint32_t addr) {
    asm volatile("ldmatrix.sync.aligned.m8n8.x4.shared.b16 {%0,%1,%2,%3}, [%4];"
                 : "=r"(r[0]), "=r"(r[1]), "=r"(r[2]), "=r"(r[3]) : "r"(addr));
}
__device__ __forceinline__ void mma_f16(float* c, const uint32_t* a, const uint32_t* b) {
    asm volatile(
        "mma.sync.aligned.m16n8k16.row.col.f32.f16.f16.f32 "
        "{%0,%1,%2,%3}, {%4,%5,%6,%7}, {%8,%9}, {%0,%1,%2,%3};"
        : "+f"(c[0]), "+f"(c[1]), "+f"(c[2]), "+f"(c[3])
        : "r"(a[0]), "r"(a[1]), "r"(a[2]), "r"(a[3]), "r"(b[0]), "r"(b[1]));
}

struct EpiPtrs { const float* bias; __half* ch; __half* cl; };
struct EpiPtrs3 { EpiPtrs p[3]; };

static constexpr int TPAD = 264;   // transpose staging row stride (halfs)

// ============================================================================
// 3-term GEMM: 256x128 CTA tile, 8 warps (4m x 2n), warp tile 64x64,
// 64-k chunks, 2-stage cp.async pipeline.
// EPI=0 (projections): z=0/1 -> 3-term, +bias, fp16 hi/lo out.
//                      z=2   -> 1-term (hi only), +bias, transpose-staged
//                               fp16 out to Vt[b][d][l].
// EPI=2: 3-term, fp32 out (+z*strC) [S-GEMM].
// ============================================================================
template <int ROWS>
__device__ __forceinline__ void load_tile(const __half* __restrict__ g,
                                          long long ld, uint32_t sdst, int tid) {
#pragma unroll
    for (int it = 0; it < ROWS * 8 / 256; it++) {
        int u = it * 256 + tid;
        int row = u >> 3, seg = u & 7;
        cp16(sdst + sw128(row * 128 + seg * 16), g + (long long)row * ld + seg * 8);
    }
}

template <int EPI>
__global__ void __launch_bounds__(256, 1)
gemm3(const __half* __restrict__ Ah, const __half* __restrict__ Al,
      const __half* __restrict__ Bh, const __half* __restrict__ Bl,
      EpiPtrs3 EP, void* __restrict__ C0,
      int K, int ldC,
      long long strA, long long strB, long long strC)
{
    constexpr int A_BYTES = 256 * 128;
    constexpr int B_BYTES = 128 * 128;
    constexpr int OFF_AH = 0;
    constexpr int OFF_AL = A_BYTES;
    constexpr int OFF_BH = 2 * A_BYTES;
    constexpr int OFF_BL = 2 * A_BYTES + B_BYTES;
    constexpr int STAGE  = 2 * A_BYTES + 2 * B_BYTES;

    extern __shared__ char smem[];
    const uint32_t sbase = s2u(smem);
    const int tid  = threadIdx.x;
    const int lane = tid & 31;
    const int warp = tid >> 5;
    const int wm = warp >> 1;
    const int wn = warp & 1;
    const int m0 = blockIdx.y * 256, n0 = blockIdx.x * 128;
    const long long z = blockIdx.z;
    // z==2 in the projection launch is the V projection: 1-term only.
    const bool oneT = (EPI == 0) && (z == 2);

    const __half* aH = Ah + z * strA + (long long)m0 * K;
    const __half* aL = Al + z * strA + (long long)m0 * K;
    const __half* bH = Bh + z * strB + (long long)n0 * K;
    const __half* bL = Bl + z * strB + (long long)n0 * K;

    float acc[4][8][4];
#pragma unroll
    for (int mt = 0; mt < 4; mt++)
#pragma unroll
        for (int nt = 0; nt < 8; nt++)
#pragma unroll
            for (int i = 0; i < 4; i++) acc[mt][nt][i] = 0.0f;

    const int nch = K >> 6;

    {
        load_tile<256>(aH, K, sbase + OFF_AH, tid);
        if (!oneT) load_tile<256>(aL, K, sbase + OFF_AL, tid);
        load_tile<128>(bH, K, sbase + OFF_BH, tid);
        if (!oneT) load_tile<128>(bL, K, sbase + OFF_BL, tid);
        cp_commit();
    }

    for (int c = 0; c < nch; c++) {
        cp_wait<0>();
        __syncthreads();

        if (c + 1 < nch) {
            uint32_t sb = sbase + ((c + 1) & 1) * STAGE;
            load_tile<256>(aH + (c + 1) * 64, K, sb + OFF_AH, tid);
            if (!oneT) load_tile<256>(aL + (c + 1) * 64, K, sb + OFF_AL, tid);
            load_tile<128>(bH + (c + 1) * 64, K, sb + OFF_BH, tid);
            if (!oneT) load_tile<128>(bL + (c + 1) * 64, K, sb + OFF_BL, tid);
            cp_commit();
        }

        const uint32_t sb  = sbase + (c & 1) * STAGE;
        const uint32_t sAh = sb + OFF_AH, sAl = sb + OFF_AL;
        const uint32_t sBh = sb + OFF_BH, sBl = sb + OFF_BL;

#pragma unroll
        for (int ks = 0; ks < 4; ks++) {
            uint32_t ah[4][4], al[4][4];
#pragma unroll
            for (int mt = 0; mt < 4; mt++) {
                uint32_t off = sw128((uint32_t)((wm * 64 + mt * 16 + (lane & 15)) * 128
                                                + (ks * 2 + (lane >> 4)) * 16));
                ldm_x4(ah[mt], sAh + off);
                if (!oneT) ldm_x4(al[mt], sAl + off);
            }
            const int g = lane >> 3;
#pragma unroll
            for (int np = 0; np < 4; np++) {
                uint32_t boff = sw128((uint32_t)(
                    (wn * 64 + np * 16 + ((g >> 1) << 3) + (lane & 7)) * 128
                    + ks * 32 + (g & 1) * 16));
                uint32_t bh[4], bl[4];
                ldm_x4(bh, sBh + boff);
                if (!oneT) ldm_x4(bl, sBl + boff);
#pragma unroll
                for (int mt = 0; mt < 4; mt++) {
                    mma_f16(acc[mt][np * 2 + 0], ah[mt], bh + 0);
                    mma_f16(acc[mt][np * 2 + 1], ah[mt], bh + 2);
                    if (!oneT) {
                        mma_f16(acc[mt][np * 2 + 0], ah[mt], bl + 0);
                        mma_f16(acc[mt][np * 2 + 1], ah[mt], bl + 2);
                        mma_f16(acc[mt][np * 2 + 0], al[mt], bh + 0);
                        mma_f16(acc[mt][np * 2 + 1], al[mt], bh + 2);
                    }
                }
            }
        }
    }

    const int rloc = wm * 64 + (lane >> 2);
    const int cloc = wn * 64 + 2 * (lane & 3);
    if (EPI == 0) {
        const EpiPtrs e = EP.p[z];
        if (z < 2) {
#pragma unroll
            for (int mt = 0; mt < 4; mt++)
#pragma unroll
                for (int nt = 0; nt < 8; nt++) {
                    int col = n0 + cloc + nt * 8;
                    float b0 = e.bias[col], b1 = e.bias[col + 1];
#pragma unroll
                    for (int hf = 0; hf < 2; hf++) {
                        int r = m0 + rloc + mt * 16 + hf * 8;
                        float v0 = acc[mt][nt][hf * 2 + 0] + b0;
                        float v1 = acc[mt][nt][hf * 2 + 1] + b1;
                        __half h0 = __float2half(v0);
                        __half h1 = __float2half(v1);
                        __half l0 = __float2half(v0 - __half2float(h0));
                        __half l1 = __float2half(v1 - __half2float(h1));
                        *(__half2*)(e.ch + (size_t)r * ldC + col) = __halves2half2(h0, h1);
                        *(__half2*)(e.cl + (size_t)r * ldC + col) = __halves2half2(l0, l1);
                    }
                }
        } else {
            // V: stage fp16 transposed in SMEM, write Vt[b][d][l] coalesced
            __half* ts = (__half*)smem;
            __syncthreads();   // mainloop SMEM reuse
#pragma unroll
            for (int mt = 0; mt < 4; mt++)
#pragma unroll
                for (int nt = 0; nt < 8; nt++) {
                    int col = cloc + nt * 8;
                    float b0 = e.bias[n0 + col], b1 = e.bias[n0 + col + 1];
#pragma unroll
                    for (int hf = 0; hf < 2; hf++) {
                        int r = rloc + mt * 16 + hf * 8;
                        ts[(size_t)col * TPAD + r] =
                            __float2half(acc[mt][nt][hf * 2 + 0] + b0);
                        ts[(size_t)(col + 1) * TPAD + r] =
                            __float2half(acc[mt][nt][hf * 2 + 1] + b1);
                    }
                }
            __syncthreads();
            const int batch = m0 >> 12;              // 4096 rows per batch
            const int l0 = m0 & 4095;
            __half* vt = e.ch + ((size_t)batch * DD) * LL;
#pragma unroll
            for (int it = 0; it < 16; it++) {
                int u = it * 256 + tid;              // 128 d-rows x 32 uint4
                int d = u >> 5, seg = u & 31;
                uint4 v = *(const uint4*)(ts + (size_t)d * TPAD + seg * 8);
                *(uint4*)(vt + (size_t)(n0 + d) * LL + l0 + seg * 8) = v;
            }
        }
    } else {
        float* Cf = (float*)C0 + z * strC;
#pragma unroll
        for (int mt = 0; mt < 4; mt++)
#pragma unroll
            for (int nt = 0; nt < 8; nt++) {
                int col = n0 + cloc + nt * 8;
#pragma unroll
                for (int hf = 0; hf < 2; hf++) {
                    int r = m0 + rloc + mt * 16 + hf * 8;
                    float2 v;
                    v.x = acc[mt][nt][hf * 2 + 0];
                    v.y = acc[mt][nt][hf * 2 + 1];
                    *(float2*)(Cf + (size_t)r * ldC + col) = v;
                }
            }
    }
}

// ============================================================================
// 1-term GEMM (frag double-buffer, 128-k chunks), O-GEMM only.
// 256x128 CTA tile, 8 warps (4m x 2n), warp tile 64x64. fp32 out (+z*strC).
// ============================================================================
template <int ROWS>
__device__ __forceinline__ void load_tile128(const __half* __restrict__ g,
                                             long long ld, uint32_t sdst, int tid) {
#pragma unroll
    for (int sub = 0; sub < 2; sub++)
#pragma unroll
        for (int it = 0; it < ROWS * 8 / 256; it++) {
            int u = it * 256 + tid;
            int row = u >> 3, seg = u & 7;
            cp16(sdst + sub * (ROWS * 128) + sw128(row * 128 + seg * 16),
                 g + (long long)row * ld + sub * 64 + seg * 8);
        }
}

__global__ void __launch_bounds__(256, 1)
gemm1(const __half* __restrict__ A, const __half* __restrict__ B,
      void* __restrict__ C0,
      int K, int ldC,
      long long strA, long long strB, long long strC)
{
    constexpr int A_SUB = 256 * 128;
    constexpr int B_SUB = 128 * 128;
    constexpr int OFF_A = 0;
    constexpr int OFF_B = 2 * A_SUB;
    constexpr int STAGE = 2 * A_SUB + 2 * B_SUB;   // 96 KB

    extern __shared__ char smem[];
    const uint32_t sbase = s2u(smem);
    const int tid  = threadIdx.x;
    const int lane = tid & 31;
    const int warp = tid >> 5;
    const int wm = warp >> 1;
    const int wn = warp & 1;
    const int m0 = blockIdx.y * 256, n0 = blockIdx.x * 128;
    const long long z = blockIdx.z;

    const __half* aP = A + z * strA + (long long)m0 * K;
    const __half* bP = B + z * strB + (long long)n0 * K;

    float acc[4][8][4];
#pragma unroll
    for (int mt = 0; mt < 4; mt++)
#pragma unroll
        for (int nt = 0; nt < 8; nt++)
#pragma unroll
            for (int i = 0; i < 4; i++) acc[mt][nt][i] = 0.0f;

    const int nch = K >> 7;
    const int g = lane >> 3;

    uint32_t aoff[4], boff[4];
#pragma unroll
    for (int kk = 0; kk < 4; kk++) {
        aoff[kk] = sw128((uint32_t)((wm * 64 + (lane & 15)) * 128
                                    + (kk * 2 + (lane >> 4)) * 16));
        boff[kk] = sw128((uint32_t)((wn * 64 + ((g >> 1) << 3) + (lane & 7)) * 128
                                    + kk * 32 + (g & 1) * 16));
    }

    load_tile128<256>(aP, K, sbase + OFF_A, tid);
    load_tile128<128>(bP, K, sbase + OFF_B, tid);
    cp_commit();

    for (int c = 0; c < nch; c++) {
        cp_wait<0>();
        __syncthreads();

        if (c + 1 < nch) {
            uint32_t sb = sbase + ((c + 1) & 1) * STAGE;
            load_tile128<256>(aP + (c + 1) * 128, K, sb + OFF_A, tid);
            load_tile128<128>(bP + (c + 1) * 128, K, sb + OFF_B, tid);
            cp_commit();
        }

        const uint32_t sb = sbase + (c & 1) * STAGE;
        const uint32_t sA = sb + OFF_A, sB = sb + OFF_B;

        uint32_t aF[2][4][4], bF[2][4][4];
#pragma unroll
        for (int mt = 0; mt < 4; mt++)
            ldm_x4(aF[0][mt], sA + aoff[0] + mt * 2048);
#pragma unroll
        for (int np = 0; np < 4; np++)
            ldm_x4(bF[0][np], sB + boff[0] + np * 2048);

#pragma unroll
        for (int ks = 0; ks < 8; ks++) {
            const int cur = ks & 1, nxt = cur ^ 1;
            if (ks < 7) {
                const int k1 = ks + 1;
                const uint32_t aSub = sA + (k1 >> 2) * A_SUB;
                const uint32_t bSub = sB + (k1 >> 2) * B_SUB;
                const int kk = k1 & 3;
#pragma unroll
                for (int mt = 0; mt < 4; mt++)
                    ldm_x4(aF[nxt][mt], aSub + aoff[kk] + mt * 2048);
#pragma unroll
                for (int np = 0; np < 4; np++)
                    ldm_x4(bF[nxt][np], bSub + boff[kk] + np * 2048);
            }
#pragma unroll
            for (int np = 0; np < 4; np++)
#pragma unroll
                for (int mt = 0; mt < 4; mt++) {
                    mma_f16(acc[mt][np * 2 + 0], aF[cur][mt], bF[cur][np] + 0);
                    mma_f16(acc[mt][np * 2 + 1], aF[cur][mt], bF[cur][np] + 2);
                }
        }
    }

    const int rloc = wm * 64 + (lane >> 2);
    const int cloc = wn * 64 + 2 * (lane & 3);
    float* Cf = (float*)C0 + z * strC;
#pragma unroll
    for (int mt = 0; mt < 4; mt++)
#pragma unroll
        for (int nt = 0; nt < 8; nt++) {
            int col = n0 + cloc + nt * 8;
#pragma unroll
            for (int hf = 0; hf < 2; hf++) {
                int r = m0 + rloc + mt * 16 + hf * 8;
                float2 v;
                v.x = acc[mt][nt][hf * 2 + 0];
                v.y = acc[mt][nt][hf * 2 + 1];
                *(float2*)(Cf + (size_t)r * ldC + col) = v;
            }
        }
}

static constexpr int SMEM3  = 2 * (2 * 256 * 128 + 2 * 128 * 128);  // 192 KB
static constexpr int SMEM1X = 2 * (2 * 32768 + 2 * 16384);          // 192 KB

// ---------------- prep kernels ----------------------------------------------
__global__ void convert_split(const float* __restrict__ x,
                              __half* __restrict__ h,
                              __half* __restrict__ l, int n4)
{
    int i = blockIdx.x * blockDim.x + threadIdx.x;
    if (i >= n4) return;
    float4 v = ((const float4*)x)[i];
    __half h0 = __float2half(v.x), h1 = __float2half(v.y);
    __half h2 = __float2half(v.z), h3 = __float2half(v.w);
    ((__half2*)h)[i * 2]     = __halves2half2(h0, h1);
    ((__half2*)h)[i * 2 + 1] = __halves2half2(h2, h3);
    ((__half2*)l)[i * 2]     = __halves2half2(
        __float2half(v.x - __half2float(h0)),
        __float2half(v.y - __half2float(h1)));
    ((__half2*)l)[i * 2 + 1] = __halves2half2(
        __float2half(v.z - __half2float(h2)),
        __float2half(v.w - __half2float(h3)));
}

__global__ void transW3(const float* __restrict__ W0, const float* __restrict__ W1,
                        const float* __restrict__ W2,
                        __half* __restrict__ th, __half* __restrict__ tl)
{
    __shared__ float t[32][33];
    const int tx = threadIdx.x, ty = threadIdx.y;      // block (32, 8)
    const int d0 = blockIdx.y * 32, e0 = blockIdx.x * 32;
    const float* W = (blockIdx.z == 0) ? W0 : (blockIdx.z == 1) ? W1 : W2;
    th += (size_t)blockIdx.z * DD * DD;
    tl += (size_t)blockIdx.z * DD * DD;
#pragma unroll
    for (int k = 0; k < 4; k++)
        t[ty + 8 * k][tx] = W[(size_t)(d0 + ty + 8 * k) * DD + e0 + tx];
    __syncthreads();
#pragma unroll
    for (int k = 0; k < 4; k++) {
        float v = t[tx][ty + 8 * k];
        __half h = __float2half(v);
        size_t o = (size_t)(e0 + ty + 8 * k) * DD + d0 + tx;
        th[o] = h;
        tl[o] = __float2half(v - __half2float(h));
    }
}

// ---------------- softmax: register-resident, fp32 S row -> fp16 P ----------
__global__ void __launch_bounds__(256)
softmax_h(const float* __restrict__ S, __half* __restrict__ P)
{
    __shared__ float red[8];
    const float* p = S + (size_t)blockIdx.x * LL;
    const int tid = threadIdx.x;
    const int lane = tid & 31, warp = tid >> 5;

    float4 v[4];
#pragma unroll
    for (int i = 0; i < 4; i++)
        v[i] = *(const float4*)(p + (i * 256 + tid) * 4);

    float m = -3.402823466e38f;
#pragma unroll
    for (int i = 0; i < 4; i++)
        m = fmaxf(m, fmaxf(fmaxf(v[i].x, v[i].y), fmaxf(v[i].z, v[i].w)));
#pragma unroll
    for (int s = 16; s > 0; s >>= 1)
        m = fmaxf(m, __shfl_xor_sync(0xffffffffu, m, s));
    if (lane == 0) red[warp] = m;
    __syncthreads();
    {
        float t = red[lane & 7];
#pragma unroll
        for (int s = 4; s > 0; s >>= 1)
            t = fmaxf(t, __shfl_xor_sync(0xffffffffu, t, s));
        m = t;
    }

    float sum = 0.0f;
#pragma unroll
    for (int i = 0; i < 4; i++) {
        v[i].x = __expf(v[i].x - m); v[i].y = __expf(v[i].y - m);
        v[i].z = __expf(v[i].z - m); v[i].w = __expf(v[i].w - m);
        sum += (v[i].x + v[i].y) + (v[i].z + v[i].w);
    }
#pragma unroll
    for (int s = 16; s > 0; s >>= 1)
        sum += __shfl_xor_sync(0xffffffffu, sum, s);
    __syncthreads();
    if (lane == 0) red[warp] = sum;
    __syncthreads();
    {
        float t = red[lane & 7];
#pragma unroll
        for (int s = 4; s > 0; s >>= 1)
            t += __shfl_xor_sync(0xffffffffu, t, s);
        sum = t;
    }
    const float inv = 1.0f / sum;

    __half2* ph = (__half2*)(P + (size_t)blockIdx.x * LL);
#pragma unroll
    for (int i = 0; i < 4; i++) {
        int idx = (i * 256 + tid) * 4;
        ph[idx / 2]     = __floats2half2_rn(v[i].x * inv, v[i].y * inv);
        ph[idx / 2 + 1] = __floats2half2_rn(v[i].z * inv, v[i].w * inv);
    }
}

// ---------------- orchestration ---------------------------------------------
extern "C" void kernel_launch(void* const* d_in, const int* in_sizes, int n_in,
                              void* d_out, int out_size)
{
    const float* X  = (const float*)d_in[0];
    const float* Wq = (const float*)d_in[1];
    const float* bq = (const float*)d_in[2];
    const float* Wk = (const float*)d_in[3];
    const float* bk = (const float*)d_in[4];
    const float* Wv = (const float*)d_in[5];
    const float* bv = (const float*)d_in[6];
    float* out = (float*)d_out;

    __half *Xh, *Xl, *Wth, *Wtl, *Qh, *Ql, *Kh, *Kl, *Vt, *P;
    float* S;
    cudaGetSymbolAddress((void**)&Xh, g_Xh);   cudaGetSymbolAddress((void**)&Xl, g_Xl);
    cudaGetSymbolAddress((void**)&Wth, g_Wth); cudaGetSymbolAddress((void**)&Wtl, g_Wtl);
    cudaGetSymbolAddress((void**)&Qh, g_Qh);   cudaGetSymbolAddress((void**)&Ql, g_Ql);
    cudaGetSymbolAddress((void**)&Kh, g_Kh);   cudaGetSymbolAddress((void**)&Kl, g_Kl);
    cudaGetSymbolAddress((void**)&Vt, g_Vt);
    cudaGetSymbolAddress((void**)&P, g_P);
    cudaGetSymbolAddress((void**)&S, g_S);

    cudaFuncSetAttribute(gemm3<0>, cudaFuncAttributeMaxDynamicSharedMemorySize, SMEM3);
    cudaFuncSetAttribute(gemm3<2>, cudaFuncAttributeMaxDynamicSharedMemorySize, SMEM3);
    cudaFuncSetAttribute(gemm1,    cudaFuncAttributeMaxDynamicSharedMemorySize, SMEM1X);

    EpiPtrs3 none{};

    // 1) split X into fp16 hi/lo
    {
        int n4 = ML * DD / 4;
        convert_split<<<(n4 + 255) / 256, 256>>>(X, Xh, Xl, n4);
    }
    // 2) transpose+split weights (one launch, z = q/k/v)
    {
        dim3 g(DD / 32, DD / 32, 3), b(32, 8);
        transW3<<<g, b>>>(Wq, Wk, Wv, Wth, Wtl);
    }
    // 3) ALL projections in one launch: z=0/1 Q/K (3-term hi/lo),
    //    z=2 V (1-term, fused transpose -> Vt[b][d][l])
    {
        EpiPtrs3 ep;
        ep.p[0] = {bq, Qh, Ql};
        ep.p[1] = {bk, Kh, Kl};
        ep.p[2] = {bv, Vt, nullptr};
        dim3 g(DD / 128, ML / 256, 3);
        gemm3<0><<<g, 256, SMEM3>>>(Xh, Xl, Wth, Wtl, ep, nullptr,
            DD, DD, 0, (long long)DD * DD, 0);
    }
    // 4) logits: S[b] = Q[b] @ K[b]^T (fp16 3-term, fp32 out)
    {
        dim3 g(LL / 128, LL / 256, BB);
        gemm3<2><<<g, 256, SMEM3>>>(Qh, Ql, Kh, Kl, none, S,
            DD, LL, (long long)LL * DD, (long long)LL * DD, (long long)LL * LL);
    }
    // 5) softmax rows -> single fp16 P
    softmax_h<<<ML, 256>>>(S, P);
    // 6) output: O[b] = P[b] @ Vt[b]^T (fp16 1-term, frag double-buffered)
    {
        dim3 g(DD / 128, LL / 256, BB);
        gemm1<<<g, 256, SMEM1X>>>(P, Vt, out,
            LL, DD, (long long)LL * LL, (long long)DD * LL, (long long)LL * DD);
    }
}

// round 14
// speedup vs baseline: 1.0735x; 1.0735x over previous
#include <cuda_runtime.h>
#include <cuda_fp16.h>
#include <cstdint>

#define BB 4
#define LL 4096
#define DD 768
#define ML (BB*LL)

// ---------------- scratch (__device__ globals; allocation-free contract) ----
__device__ __half g_Xh[(size_t)ML * DD], g_Xl[(size_t)ML * DD];
__device__ __half g_Wth[3][(size_t)DD * DD], g_Wtl[3][(size_t)DD * DD];
__device__ __half g_Qh[(size_t)ML * DD], g_Ql[(size_t)ML * DD];
__device__ __half g_Kh[(size_t)ML * DD], g_Kl[(size_t)ML * DD];
__device__ __half g_Vt[(size_t)ML * DD];              // [b][d][l] fp16
__device__ float  g_S [(size_t)BB * LL * LL];
__device__ __half g_P [(size_t)BB * LL * LL];

// ---------------- helpers (base-family ISA only) -----------------------------
__device__ __forceinline__ uint32_t s2u(const void* p) {
    uint32_t a;
    asm("{ .reg .u64 t; cvta.to.shared.u64 t, %1; cvt.u32.u64 %0, t; }"
        : "=r"(a) : "l"(p));
    return a;
}
__device__ __forceinline__ uint32_t sw128(uint32_t off) {
    return off ^ ((off >> 3) & 0x70);
}
__device__ __forceinline__ void cp16(uint32_t saddr, const void* g) {
    asm volatile("cp.async.cg.shared.global [%0], [%1], 16;" :: "r"(saddr), "l"(g));
}
__device__ __forceinline__ void cp_commit() {
    asm volatile("cp.async.commit_group;");
}
template <int N>
__device__ __forceinline__ void cp_wait() {
    asm volatile("cp.async.wait_group %0;" :: "n"(N));
}
__device__ __forceinline__ void ldm_x4(uint32_t* r, uint32_t addr) {
    asm volatile("ldmatrix.sync.aligned.m8n8.x4.shared.b16 {%0,%1,%2,%3}, [%4];"
                 : "=r"(r[0]), "=r"(r[1]), "=r"(r[2]), "=r"(r[3]) : "r"(addr));
}
__device__ __forceinline__ void mma_f16(float* c, const uint32_t* a, const uint32_t* b) {
    asm volatile(
        "mma.sync.aligned.m16n8k16.row.col.f32.f16.f16.f32 "
        "{%0,%1,%2,%3}, {%4,%5,%6,%7}, {%8,%9}, {%0,%1,%2,%3};"
        : "+f"(c[0]), "+f"(c[1]), "+f"(c[2]), "+f"(c[3])
        : "r"(a[0]), "r"(a[1]), "r"(a[2]), "r"(a[3]), "r"(b[0]), "r"(b[1]));
}

struct EpiPtrs { const float* bias; __half* ch; __half* cl; };
struct EpiPtrs3 { EpiPtrs p[3]; };

static constexpr int TPAD = 264;   // transpose staging row stride (halfs)

// ============================================================================
// 3-term GEMM (R9/R11 winner config): 256x128 CTA tile, 8 warps (4m x 2n),
// warp tile 64x64, 64-k chunks, 2-stage cp.async pipeline.
// EPI=0: +bias, fp16 hi/lo out (per-z ptrs). EPI=2: fp32 out (+z*strC).
// ============================================================================
template <int ROWS>
__device__ __forceinline__ void load_tile(const __half* __restrict__ g,
                                          long long ld, uint32_t sdst, int tid) {
#pragma unroll
    for (int it = 0; it < ROWS * 8 / 256; it++) {
        int u = it * 256 + tid;
        int row = u >> 3, seg = u & 7;
        cp16(sdst + sw128(row * 128 + seg * 16), g + (long long)row * ld + seg * 8);
    }
}

template <int EPI>
__global__ void __launch_bounds__(256, 1)
gemm3(const __half* __restrict__ Ah, const __half* __restrict__ Al,
      const __half* __restrict__ Bh, const __half* __restrict__ Bl,
      EpiPtrs3 EP, void* __restrict__ C0,
      int K, int ldC,
      long long strA, long long strB, long long strC)
{
    constexpr int A_BYTES = 256 * 128;
    constexpr int B_BYTES = 128 * 128;
    constexpr int OFF_AH = 0;
    constexpr int OFF_AL = A_BYTES;
    constexpr int OFF_BH = 2 * A_BYTES;
    constexpr int OFF_BL = 2 * A_BYTES + B_BYTES;
    constexpr int STAGE  = 2 * A_BYTES + 2 * B_BYTES;

    extern __shared__ char smem[];
    const uint32_t sbase = s2u(smem);
    const int tid  = threadIdx.x;
    const int lane = tid & 31;
    const int warp = tid >> 5;
    const int wm = warp >> 1;
    const int wn = warp & 1;
    const int m0 = blockIdx.y * 256, n0 = blockIdx.x * 128;
    const long long z = blockIdx.z;

    const __half* aH = Ah + z * strA + (long long)m0 * K;
    const __half* aL = Al + z * strA + (long long)m0 * K;
    const __half* bH = Bh + z * strB + (long long)n0 * K;
    const __half* bL = Bl + z * strB + (long long)n0 * K;

    float acc[4][8][4];
#pragma unroll
    for (int mt = 0; mt < 4; mt++)
#pragma unroll
        for (int nt = 0; nt < 8; nt++)
#pragma unroll
            for (int i = 0; i < 4; i++) acc[mt][nt][i] = 0.0f;

    const int nch = K >> 6;

    {
        load_tile<256>(aH, K, sbase + OFF_AH, tid);
        load_tile<256>(aL, K, sbase + OFF_AL, tid);
        load_tile<128>(bH, K, sbase + OFF_BH, tid);
        load_tile<128>(bL, K, sbase + OFF_BL, tid);
        cp_commit();
    }

    for (int c = 0; c < nch; c++) {
        cp_wait<0>();
        __syncthreads();

        if (c + 1 < nch) {
            uint32_t sb = sbase + ((c + 1) & 1) * STAGE;
            load_tile<256>(aH + (c + 1) * 64, K, sb + OFF_AH, tid);
            load_tile<256>(aL + (c + 1) * 64, K, sb + OFF_AL, tid);
            load_tile<128>(bH + (c + 1) * 64, K, sb + OFF_BH, tid);
            load_tile<128>(bL + (c + 1) * 64, K, sb + OFF_BL, tid);
            cp_commit();
        }

        const uint32_t sb  = sbase + (c & 1) * STAGE;
        const uint32_t sAh = sb + OFF_AH, sAl = sb + OFF_AL;
        const uint32_t sBh = sb + OFF_BH, sBl = sb + OFF_BL;

#pragma unroll
        for (int ks = 0; ks < 4; ks++) {
            uint32_t ah[4][4], al[4][4];
#pragma unroll
            for (int mt = 0; mt < 4; mt++) {
                uint32_t off = sw128((uint32_t)((wm * 64 + mt * 16 + (lane & 15)) * 128
                                                + (ks * 2 + (lane >> 4)) * 16));
                ldm_x4(ah[mt], sAh + off);
                ldm_x4(al[mt], sAl + off);
            }
            const int g = lane >> 3;
#pragma unroll
            for (int np = 0; np < 4; np++) {
                uint32_t boff = sw128((uint32_t)(
                    (wn * 64 + np * 16 + ((g >> 1) << 3) + (lane & 7)) * 128
                    + ks * 32 + (g & 1) * 16));
                uint32_t bh[4], bl[4];
                ldm_x4(bh, sBh + boff);
                ldm_x4(bl, sBl + boff);
#pragma unroll
                for (int mt = 0; mt < 4; mt++) {
                    mma_f16(acc[mt][np * 2 + 0], ah[mt], bh + 0);
                    mma_f16(acc[mt][np * 2 + 1], ah[mt], bh + 2);
                    mma_f16(acc[mt][np * 2 + 0], ah[mt], bl + 0);
                    mma_f16(acc[mt][np * 2 + 1], ah[mt], bl + 2);
                    mma_f16(acc[mt][np * 2 + 0], al[mt], bh + 0);
                    mma_f16(acc[mt][np * 2 + 1], al[mt], bh + 2);
                }
            }
        }
    }

    const int rloc = wm * 64 + (lane >> 2);
    const int cloc = wn * 64 + 2 * (lane & 3);
    if (EPI == 0) {
        const EpiPtrs e = EP.p[z];
#pragma unroll
        for (int mt = 0; mt < 4; mt++)
#pragma unroll
            for (int nt = 0; nt < 8; nt++) {
                int col = n0 + cloc + nt * 8;
                float b0 = e.bias[col], b1 = e.bias[col + 1];
#pragma unroll
                for (int hf = 0; hf < 2; hf++) {
                    int r = m0 + rloc + mt * 16 + hf * 8;
                    float v0 = acc[mt][nt][hf * 2 + 0] + b0;
                    float v1 = acc[mt][nt][hf * 2 + 1] + b1;
                    __half h0 = __float2half(v0);
                    __half h1 = __float2half(v1);
                    __half l0 = __float2half(v0 - __half2float(h0));
                    __half l1 = __float2half(v1 - __half2float(h1));
                    *(__half2*)(e.ch + (size_t)r * ldC + col) = __halves2half2(h0, h1);
                    *(__half2*)(e.cl + (size_t)r * ldC + col) = __halves2half2(l0, l1);
                }
            }
    } else {
        float* Cf = (float*)C0 + z * strC;
#pragma unroll
        for (int mt = 0; mt < 4; mt++)
#pragma unroll
            for (int nt = 0; nt < 8; nt++) {
                int col = n0 + cloc + nt * 8;
#pragma unroll
                for (int hf = 0; hf < 2; hf++) {
                    int r = m0 + rloc + mt * 16 + hf * 8;
                    float2 v;
                    v.x = acc[mt][nt][hf * 2 + 0];
                    v.y = acc[mt][nt][hf * 2 + 1];
                    *(float2*)(Cf + (size_t)r * ldC + col) = v;
                }
            }
    }
}

// ============================================================================
// 1-term GEMM (R11: frag double-buffer, 128-k chunks). 256x128 CTA, 8 warps.
// EPI=1: +bias, transpose-staged fp16 out to Vt[b][d][l].
// EPI=2: fp32 out (+z*strC).
// ============================================================================
template <int ROWS>
__device__ __forceinline__ void load_tile128(const __half* __restrict__ g,
                                             long long ld, uint32_t sdst, int tid) {
#pragma unroll
    for (int sub = 0; sub < 2; sub++)
#pragma unroll
        for (int it = 0; it < ROWS * 8 / 256; it++) {
            int u = it * 256 + tid;
            int row = u >> 3, seg = u & 7;
            cp16(sdst + sub * (ROWS * 128) + sw128(row * 128 + seg * 16),
                 g + (long long)row * ld + sub * 64 + seg * 8);
        }
}

template <int EPI>
__global__ void __launch_bounds__(256, 1)
gemm1(const __half* __restrict__ A, const __half* __restrict__ B,
      const float* __restrict__ bias, void* __restrict__ C0,
      int K, int ldC,
      long long strA, long long strB, long long strC)
{
    constexpr int A_SUB = 256 * 128;
    constexpr int B_SUB = 128 * 128;
    constexpr int OFF_A = 0;
    constexpr int OFF_B = 2 * A_SUB;
    constexpr int STAGE = 2 * A_SUB + 2 * B_SUB;   // 96 KB

    extern __shared__ char smem[];
    const uint32_t sbase = s2u(smem);
    const int tid  = threadIdx.x;
    const int lane = tid & 31;
    const int warp = tid >> 5;
    const int wm = warp >> 1;
    const int wn = warp & 1;
    const int m0 = blockIdx.y * 256, n0 = blockIdx.x * 128;
    const long long z = blockIdx.z;

    const __half* aP = A + z * strA + (long long)m0 * K;
    const __half* bP = B + z * strB + (long long)n0 * K;

    float acc[4][8][4];
#pragma unroll
    for (int mt = 0; mt < 4; mt++)
#pragma unroll
        for (int nt = 0; nt < 8; nt++)
#pragma unroll
            for (int i = 0; i < 4; i++) acc[mt][nt][i] = 0.0f;

    const int nch = K >> 7;
    const int g = lane >> 3;

    uint32_t aoff[4], boff[4];
#pragma unroll
    for (int kk = 0; kk < 4; kk++) {
        aoff[kk] = sw128((uint32_t)((wm * 64 + (lane & 15)) * 128
                                    + (kk * 2 + (lane >> 4)) * 16));
        boff[kk] = sw128((uint32_t)((wn * 64 + ((g >> 1) << 3) + (lane & 7)) * 128
                                    + kk * 32 + (g & 1) * 16));
    }

    load_tile128<256>(aP, K, sbase + OFF_A, tid);
    load_tile128<128>(bP, K, sbase + OFF_B, tid);
    cp_commit();

    for (int c = 0; c < nch; c++) {
        cp_wait<0>();
        __syncthreads();

        if (c + 1 < nch) {
            uint32_t sb = sbase + ((c + 1) & 1) * STAGE;
            load_tile128<256>(aP + (c + 1) * 128, K, sb + OFF_A, tid);
            load_tile128<128>(bP + (c + 1) * 128, K, sb + OFF_B, tid);
            cp_commit();
        }

        const uint32_t sb = sbase + (c & 1) * STAGE;
        const uint32_t sA = sb + OFF_A, sB = sb + OFF_B;

        uint32_t aF[2][4][4], bF[2][4][4];
#pragma unroll
        for (int mt = 0; mt < 4; mt++)
            ldm_x4(aF[0][mt], sA + aoff[0] + mt * 2048);
#pragma unroll
        for (int np = 0; np < 4; np++)
            ldm_x4(bF[0][np], sB + boff[0] + np * 2048);

#pragma unroll
        for (int ks = 0; ks < 8; ks++) {
            const int cur = ks & 1, nxt = cur ^ 1;
            if (ks < 7) {
                const int k1 = ks + 1;
                const uint32_t aSub = sA + (k1 >> 2) * A_SUB;
                const uint32_t bSub = sB + (k1 >> 2) * B_SUB;
                const int kk = k1 & 3;
#pragma unroll
                for (int mt = 0; mt < 4; mt++)
                    ldm_x4(aF[nxt][mt], aSub + aoff[kk] + mt * 2048);
#pragma unroll
                for (int np = 0; np < 4; np++)
                    ldm_x4(bF[nxt][np], bSub + boff[kk] + np * 2048);
            }
#pragma unroll
            for (int np = 0; np < 4; np++)
#pragma unroll
                for (int mt = 0; mt < 4; mt++) {
                    mma_f16(acc[mt][np * 2 + 0], aF[cur][mt], bF[cur][np] + 0);
                    mma_f16(acc[mt][np * 2 + 1], aF[cur][mt], bF[cur][np] + 2);
                }
        }
    }

    const int rloc = wm * 64 + (lane >> 2);
    const int cloc = wn * 64 + 2 * (lane & 3);
    if (EPI == 1) {
        __half* ts = (__half*)smem;
        __syncthreads();
#pragma unroll
        for (int mt = 0; mt < 4; mt++)
#pragma unroll
            for (int nt = 0; nt < 8; nt++) {
                int col = cloc + nt * 8;
                float b0 = bias[n0 + col], b1 = bias[n0 + col + 1];
#pragma unroll
                for (int hf = 0; hf < 2; hf++) {
                    int r = rloc + mt * 16 + hf * 8;
                    ts[(size_t)col * TPAD + r] =
                        __float2half(acc[mt][nt][hf * 2 + 0] + b0);
                    ts[(size_t)(col + 1) * TPAD + r] =
                        __float2half(acc[mt][nt][hf * 2 + 1] + b1);
                }
            }
        __syncthreads();
        const int batch = m0 >> 12;
        const int l0 = m0 & 4095;
        __half* vt = (__half*)C0 + ((size_t)batch * DD) * LL;
#pragma unroll
        for (int it = 0; it < 16; it++) {
            int u = it * 256 + tid;
            int d = u >> 5, seg = u & 31;
            uint4 v = *(const uint4*)(ts + (size_t)d * TPAD + seg * 8);
            *(uint4*)(vt + (size_t)(n0 + d) * LL + l0 + seg * 8) = v;
        }
    } else {
        float* Cf = (float*)C0 + z * strC;
#pragma unroll
        for (int mt = 0; mt < 4; mt++)
#pragma unroll
            for (int nt = 0; nt < 8; nt++) {
                int col = n0 + cloc + nt * 8;
#pragma unroll
                for (int hf = 0; hf < 2; hf++) {
                    int r = m0 + rloc + mt * 16 + hf * 8;
                    float2 v;
                    v.x = acc[mt][nt][hf * 2 + 0];
                    v.y = acc[mt][nt][hf * 2 + 1];
                    *(float2*)(Cf + (size_t)r * ldC + col) = v;
                }
            }
    }
}

static constexpr int SMEM3  = 2 * (2 * 256 * 128 + 2 * 128 * 128);  // 192 KB
static constexpr int SMEM1X = 2 * (2 * 32768 + 2 * 16384);          // 192 KB

// ---------------- prep kernels ----------------------------------------------
__global__ void convert_split(const float* __restrict__ x,
                              __half* __restrict__ h,
                              __half* __restrict__ l, int n4)
{
    int i = blockIdx.x * blockDim.x + threadIdx.x;
    if (i >= n4) return;
    float4 v = ((const float4*)x)[i];
    __half h0 = __float2half(v.x), h1 = __float2half(v.y);
    __half h2 = __float2half(v.z), h3 = __float2half(v.w);
    ((__half2*)h)[i * 2]     = __halves2half2(h0, h1);
    ((__half2*)h)[i * 2 + 1] = __halves2half2(h2, h3);
    ((__half2*)l)[i * 2]     = __halves2half2(
        __float2half(v.x - __half2float(h0)),
        __float2half(v.y - __half2float(h1)));
    ((__half2*)l)[i * 2 + 1] = __halves2half2(
        __float2half(v.z - __half2float(h2)),
        __float2half(v.w - __half2float(h3)));
}

__global__ void transW3(const float* __restrict__ W0, const float* __restrict__ W1,
                        const float* __restrict__ W2,
                        __half* __restrict__ th, __half* __restrict__ tl)
{
    __shared__ float t[32][33];
    const int tx = threadIdx.x, ty = threadIdx.y;      // block (32, 8)
    const int d0 = blockIdx.y * 32, e0 = blockIdx.x * 32;
    const float* W = (blockIdx.z == 0) ? W0 : (blockIdx.z == 1) ? W1 : W2;
    th += (size_t)blockIdx.z * DD * DD;
    tl += (size_t)blockIdx.z * DD * DD;
#pragma unroll
    for (int k = 0; k < 4; k++)
        t[ty + 8 * k][tx] = W[(size_t)(d0 + ty + 8 * k) * DD + e0 + tx];
    __syncthreads();
#pragma unroll
    for (int k = 0; k < 4; k++) {
        float v = t[tx][ty + 8 * k];
        __half h = __float2half(v);
        size_t o = (size_t)(e0 + ty + 8 * k) * DD + d0 + tx;
        th[o] = h;
        tl[o] = __float2half(v - __half2float(h));
    }
}

// ---------------- softmax: register-resident, fp32 S row -> fp16 P ----------
__global__ void __launch_bounds__(256)
softmax_h(const float* __restrict__ S, __half* __restrict__ P)
{
    __shared__ float red[8];
    const float* p = S + (size_t)blockIdx.x * LL;
    const int tid = threadIdx.x;
    const int lane = tid & 31, warp = tid >> 5;

    float4 v[4];
#pragma unroll
    for (int i = 0; i < 4; i++)
        v[i] = *(const float4*)(p + (i * 256 + tid) * 4);

    float m = -3.402823466e38f;
#pragma unroll
    for (int i = 0; i < 4; i++)
        m = fmaxf(m, fmaxf(fmaxf(v[i].x, v[i].y), fmaxf(v[i].z, v[i].w)));
#pragma unroll
    for (int s = 16; s > 0; s >>= 1)
        m = fmaxf(m, __shfl_xor_sync(0xffffffffu, m, s));
    if (lane == 0) red[warp] = m;
    __syncthreads();
    {
        float t = red[lane & 7];
#pragma unroll
        for (int s = 4; s > 0; s >>= 1)
            t = fmaxf(t, __shfl_xor_sync(0xffffffffu, t, s));
        m = t;
    }

    float sum = 0.0f;
#pragma unroll
    for (int i = 0; i < 4; i++) {
        v[i].x = __expf(v[i].x - m); v[i].y = __expf(v[i].y - m);
        v[i].z = __expf(v[i].z - m); v[i].w = __expf(v[i].w - m);
        sum += (v[i].x + v[i].y) + (v[i].z + v[i].w);
    }
#pragma unroll
    for (int s = 16; s > 0; s >>= 1)
        sum += __shfl_xor_sync(0xffffffffu, sum, s);
    __syncthreads();
    if (lane == 0) red[warp] = sum;
    __syncthreads();
    {
        float t = red[lane & 7];
#pragma unroll
        for (int s = 4; s > 0; s >>= 1)
            t += __shfl_xor_sync(0xffffffffu, t, s);
        sum = t;
    }
    const float inv = 1.0f / sum;

    __half2* ph = (__half2*)(P + (size_t)blockIdx.x * LL);
#pragma unroll
    for (int i = 0; i < 4; i++) {
        int idx = (i * 256 + tid) * 4;
        ph[idx / 2]     = __floats2half2_rn(v[i].x * inv, v[i].y * inv);
        ph[idx / 2 + 1] = __floats2half2_rn(v[i].z * inv, v[i].w * inv);
    }
}

// ---------------- orchestration (fork/join dual-stream) ---------------------
extern "C" void kernel_launch(void* const* d_in, const int* in_sizes, int n_in,
                              void* d_out, int out_size)
{
    const float* X  = (const float*)d_in[0];
    const float* Wq = (const float*)d_in[1];
    const float* bq = (const float*)d_in[2];
    const float* Wk = (const float*)d_in[3];
    const float* bk = (const float*)d_in[4];
    const float* Wv = (const float*)d_in[5];
    const float* bv = (const float*)d_in[6];
    float* out = (float*)d_out;

    __half *Xh, *Xl, *Wth, *Wtl, *Qh, *Ql, *Kh, *Kl, *Vt, *P;
    float* S;
    cudaGetSymbolAddress((void**)&Xh, g_Xh);   cudaGetSymbolAddress((void**)&Xl, g_Xl);
    cudaGetSymbolAddress((void**)&Wth, g_Wth); cudaGetSymbolAddress((void**)&Wtl, g_Wtl);
    cudaGetSymbolAddress((void**)&Qh, g_Qh);   cudaGetSymbolAddress((void**)&Ql, g_Ql);
    cudaGetSymbolAddress((void**)&Kh, g_Kh);   cudaGetSymbolAddress((void**)&Kl, g_Kl);
    cudaGetSymbolAddress((void**)&Vt, g_Vt);
    cudaGetSymbolAddress((void**)&P, g_P);
    cudaGetSymbolAddress((void**)&S, g_S);

    cudaFuncSetAttribute(gemm3<0>, cudaFuncAttributeMaxDynamicSharedMemorySize, SMEM3);
    cudaFuncSetAttribute(gemm3<2>, cudaFuncAttributeMaxDynamicSharedMemorySize, SMEM3);
    cudaFuncSetAttribute(gemm1<1>, cudaFuncAttributeMaxDynamicSharedMemorySize, SMEM1X);
    cudaFuncSetAttribute(gemm1<2>, cudaFuncAttributeMaxDynamicSharedMemorySize, SMEM1X);

    EpiPtrs3 none{};

    // second stream + events for fork/join (created per call; host-side only)
    cudaStream_t s2;
    cudaStreamCreateWithFlags(&s2, cudaStreamNonBlocking);
    cudaEvent_t e0, eX, eW, eV;
    cudaEventCreateWithFlags(&e0, cudaEventDisableTiming);
    cudaEventCreateWithFlags(&eX, cudaEventDisableTiming);
    cudaEventCreateWithFlags(&eW, cudaEventDisableTiming);
    cudaEventCreateWithFlags(&eV, cudaEventDisableTiming);

    // fork: bring s2 into the captured graph
    cudaEventRecord(e0, 0);
    cudaStreamWaitEvent(s2, e0, 0);

    // s2: transpose+split weights (independent of X)
    {
        dim3 g(DD / 32, DD / 32, 3), b(32, 8);
        transW3<<<g, b, 0, s2>>>(Wq, Wk, Wv, Wth, Wtl);
    }
    cudaEventRecord(eW, s2);

    // s0: split X into fp16 hi/lo (concurrent with transW3)
    {
        int n4 = ML * DD / 4;
        convert_split<<<(n4 + 255) / 256, 256>>>(X, Xh, Xl, n4);
    }
    cudaEventRecord(eX, 0);

    // s2: V projection (needs Xh [eX] + Wth[2] [already ordered on s2])
    cudaStreamWaitEvent(s2, eX, 0);
    {
        dim3 g(DD / 128, ML / 256, 1);
        gemm1<1><<<g, 256, SMEM1X, s2>>>(Xh, Wth + 2 * (size_t)DD * DD, bv, Vt,
            DD, DD, 0, 0, 0);
    }
    cudaEventRecord(eV, s2);

    // s0: Q/K projections (need transW3 done)
    cudaStreamWaitEvent(0, eW, 0);
    {
        EpiPtrs3 ep;
        ep.p[0] = {bq, Qh, Ql};
        ep.p[1] = {bk, Kh, Kl};
        ep.p[2] = {};
        dim3 g(DD / 128, ML / 256, 2);
        gemm3<0><<<g, 256, SMEM3>>>(Xh, Xl, Wth, Wtl, ep, nullptr,
            DD, DD, 0, (long long)DD * DD, 0);
    }
    // s0: logits S = Q K^T (V proj overlaps this on s2)
    {
        dim3 g(LL / 128, LL / 256, BB);
        gemm3<2><<<g, 256, SMEM3>>>(Qh, Ql, Kh, Kl, none, S,
            DD, LL, (long long)LL * DD, (long long)LL * DD, (long long)LL * LL);
    }
    // s0: softmax rows -> fp16 P
    softmax_h<<<ML, 256>>>(S, P);
    // join: O needs Vt
    cudaStreamWaitEvent(0, eV, 0);
    // s0: O = P @ Vt^T
    {
        dim3 g(DD / 128, LL / 256, BB);
        gemm1<2><<<g, 256, SMEM1X>>>(P, Vt, nullptr, out,
            LL, DD, (long long)LL * LL, (long long)DD * LL, (long long)LL * DD);
    }
    // NOTE: stream/events intentionally not destroyed here — kernel_launch is
    // invoked only a handful of times (correctness + capture); destroying
    // capture-referenced events mid-capture is unsafe. Host-side leak only.
}